// round 7
// baseline (speedup 1.0000x reference)
#include <cuda_runtime.h>
#include <cuda_fp16.h>
#include <cstdint>

#define BATCH   16384
#define NCONDS  50
#define EMB_DIM 64
#define NROWS   100002                    // NEVENTS + 2
#define IN_ROW  (1 + NCONDS)             // 51 int32 per batch row
#define OUT_ROW ((1 + NCONDS) * EMB_DIM) // 3264 floats per batch row
#define PF      4                        // prefetch depth (stages)
#define NSTAGE  (NCONDS / 2)             // 25 stages, 2 conds per stage

// Row-normalized table in fp16: halves the gather read traffic (25.6->12.8 MB
// resident; 214->107 MB of L2 reads in the main pass).
__device__ __half g_ntab[(size_t)NROWS * EMB_DIM];

// ---------------- Pass 1: normalize all table rows -> fp16 ----------------
// 8 lanes per row (8 floats each), 4 rows per warp.
__global__ void __launch_bounds__(256)
norm_table_kernel(const float* __restrict__ table)
{
    const int warp = (blockIdx.x * blockDim.x + threadIdx.x) >> 5;
    const int lane = threadIdx.x & 31;
    const int row  = warp * 4 + (lane >> 3);
    const int hl   = lane & 7;
    if (row >= NROWS) return;

    const float* src = table + (size_t)row * EMB_DIM + hl * 8;
    const float4 v0 = *reinterpret_cast<const float4*>(src);
    const float4 v1 = *reinterpret_cast<const float4*>(src + 4);

    float ss = v0.x*v0.x + v0.y*v0.y + v0.z*v0.z + v0.w*v0.w
             + v1.x*v1.x + v1.y*v1.y + v1.z*v1.z + v1.w*v1.w;
    #pragma unroll
    for (int o = 4; o; o >>= 1)
        ss += __shfl_xor_sync(0xffffffffu, ss, o);   // within 8-lane group
    const float inv = rsqrtf(ss);

    union { uint4 u; __half2 h[4]; } pk;
    pk.h[0] = __floats2half2_rn(v0.x * inv, v0.y * inv);
    pk.h[1] = __floats2half2_rn(v0.z * inv, v0.w * inv);
    pk.h[2] = __floats2half2_rn(v1.x * inv, v1.y * inv);
    pk.h[3] = __floats2half2_rn(v1.z * inv, v1.w * inv);
    *reinterpret_cast<uint4*>(g_ntab + (size_t)row * EMB_DIM + hl * 8) = pk.u;
}

// ---------------- Pass 2: gather fp16 normalized rows + dot + scale --------
// One warp per batch row; each half-warp owns one condition per stage
// (16 lanes x 4 halves = one 128B line per cond row). Prefetch ring depth PF.
__global__ void __launch_bounds__(256)
cond_filter_kernel(const int* __restrict__ inp,
                   const float* __restrict__ table,
                   float* __restrict__ out)
{
    const int warp = (blockIdx.x * blockDim.x + threadIdx.x) >> 5;
    const int lane = threadIdx.x & 31;
    if (warp >= BATCH) return;

    const int hl   = lane & 15;   // lane within half-warp
    const int half = lane >> 4;   // which half-warp (0/1)

    const int* __restrict__ row  = inp + (size_t)warp * IN_ROW;
    float* __restrict__     orow = out + (size_t)warp * OUT_ROW;

    // ---- Prologue: start PF condition gathers immediately ----
    uint2 ring[PF];
    #pragma unroll
    for (int p = 0; p < PF; p++) {
        const int cidx = __ldg(row + 1 + 2 * p + half);
        ring[p] = *reinterpret_cast<const uint2*>(
            g_ntab + (size_t)cidx * EMB_DIM + hl * 4);
    }

    // ---- Event: raw fp32 copy to output; normalized fp16 row for the dot ----
    const int eidx = __ldg(row);
    if (half == 0) {
        const float4 ev = *reinterpret_cast<const float4*>(
            table + (size_t)eidx * EMB_DIM + hl * 4);
        *reinterpret_cast<float4*>(orow + hl * 4) = ev;
    }
    const uint2 enr = *reinterpret_cast<const uint2*>(
        g_ntab + (size_t)eidx * EMB_DIM + hl * 4);
    const float2 en0 = __half22float2(*reinterpret_cast<const __half2*>(&enr.x));
    const float2 en1 = __half22float2(*reinterpret_cast<const __half2*>(&enr.y));

    // ---- Stages: consume s, prefetch s+PF ----
    float* __restrict__ crow = orow + EMB_DIM;
    #pragma unroll
    for (int s = 0; s < NSTAGE; s++) {
        const uint2 cr = ring[s % PF];
        if (s + PF < NSTAGE) {
            const int cidx = __ldg(row + 1 + 2 * (s + PF) + half);
            ring[s % PF] = *reinterpret_cast<const uint2*>(
                g_ntab + (size_t)cidx * EMB_DIM + hl * 4);
        }

        const float2 c0 = __half22float2(*reinterpret_cast<const __half2*>(&cr.x));
        const float2 c1 = __half22float2(*reinterpret_cast<const __half2*>(&cr.y));

        float dt = c0.x * en0.x + c0.y * en0.y + c1.x * en1.x + c1.y * en1.y;
        #pragma unroll
        for (int o = 8; o; o >>= 1)
            dt += __shfl_xor_sync(0xffffffffu, dt, o);   // within half-warp

        // filtered = cond_nrm * score = cn * dot(en, cn)
        *reinterpret_cast<float4*>(
            crow + (size_t)(2 * s + half) * EMB_DIM + hl * 4) =
            make_float4(c0.x * dt, c0.y * dt, c1.x * dt, c1.y * dt);
    }
}

extern "C" void kernel_launch(void* const* d_in, const int* in_sizes, int n_in,
                              void* d_out, int out_size)
{
    const int*   inp   = (const int*)d_in[0];     // (16384, 51) int32
    const float* table = (const float*)d_in[1];   // (100002, 64) float32
    float*       out   = (float*)d_out;           // (16384, 3264) float32

    // Pass 1: normalize table -> fp16 (32 rows per 256-thread block)
    const int nblocks = (NROWS + 31) / 32;
    norm_table_kernel<<<nblocks, 256>>>(table);

    // Pass 2: gather + filter
    const int threads = 256;
    const int total_threads = BATCH * 32;
    const int blocks = (total_threads + threads - 1) / threads;
    cond_filter_kernel<<<blocks, threads>>>(inp, table, out);
}

// round 11
// speedup vs baseline: 1.1762x; 1.1762x over previous
#include <cuda_runtime.h>
#include <cstdint>

#define BATCH   16384
#define NCONDS  50
#define EMB_DIM 64
#define IN_ROW  (1 + NCONDS)             // 51 int32 per batch row
#define OUT_ROW ((1 + NCONDS) * EMB_DIM) // 3264 floats per batch row
#define PF      4                        // software-pipeline depth
#define NSTAGE  (NCONDS / 2)             // 25 stages, 2 conds per stage

// Single-pass: one warp per batch row; each half-warp (16 lanes x float4)
// owns one condition per stage. Register prefetch ring keeps PF gathers in
// flight. All output stores are streaming (evict-first) so the 214 MB write
// stream doesn't evict the 25.6 MB table from L2.
__global__ void __launch_bounds__(256)
cond_filter_kernel(const int* __restrict__ inp,
                   const float* __restrict__ table,
                   float* __restrict__ out)
{
    const int warp = (blockIdx.x * blockDim.x + threadIdx.x) >> 5;
    const int lane = threadIdx.x & 31;
    if (warp >= BATCH) return;

    const int hl   = lane & 15;   // lane within half-warp
    const int half = lane >> 4;   // which half-warp (0/1)

    const int* __restrict__ row  = inp + (size_t)warp * IN_ROW;
    float* __restrict__     orow = out + (size_t)warp * OUT_ROW;

    // ---- Prologue: start PF condition gathers immediately ----
    float4 ring[PF];
    #pragma unroll
    for (int p = 0; p < PF; p++) {
        const int cidx = __ldg(row + 1 + 2 * p + half);
        ring[p] = *reinterpret_cast<const float4*>(
            table + (size_t)cidx * EMB_DIM + hl * 4);
    }

    // ---- Event: raw copy out + normalize in registers (overlaps gathers) ----
    const int eidx = __ldg(row);
    const float4 ev = *reinterpret_cast<const float4*>(
        table + (size_t)eidx * EMB_DIM + hl * 4);
    if (half == 0)
        __stcs(reinterpret_cast<float4*>(orow + hl * 4), ev);

    float ss = ev.x * ev.x + ev.y * ev.y + ev.z * ev.z + ev.w * ev.w;
    #pragma unroll
    for (int o = 8; o; o >>= 1)
        ss += __shfl_xor_sync(0xffffffffu, ss, o);   // within half-warp
    const float einv = rsqrtf(ss);
    const float4 en = make_float4(ev.x * einv, ev.y * einv,
                                  ev.z * einv, ev.w * einv);

    // ---- Stages: consume s, prefetch s+PF ----
    float* __restrict__ crow = orow + EMB_DIM;
    #pragma unroll
    for (int s = 0; s < NSTAGE; s++) {
        const float4 cv = ring[s % PF];
        if (s + PF < NSTAGE) {
            const int cidx = __ldg(row + 1 + 2 * (s + PF) + half);
            ring[s % PF] = *reinterpret_cast<const float4*>(
                table + (size_t)cidx * EMB_DIM + hl * 4);
        }

        float s2 = cv.x * cv.x + cv.y * cv.y + cv.z * cv.z + cv.w * cv.w;
        float dt = cv.x * en.x + cv.y * en.y + cv.z * en.z + cv.w * en.w;
        #pragma unroll
        for (int o = 8; o; o >>= 1) {
            s2 += __shfl_xor_sync(0xffffffffu, s2, o);
            dt += __shfl_xor_sync(0xffffffffu, dt, o);
        }
        const float cinv  = rsqrtf(s2);
        // filtered = cond_nrm * score = cv * (dt * cinv^2)
        const float scale = dt * cinv * cinv;

        __stcs(reinterpret_cast<float4*>(
                   crow + (size_t)(2 * s + half) * EMB_DIM + hl * 4),
               make_float4(cv.x * scale, cv.y * scale, cv.z * scale, cv.w * scale));
    }
}

extern "C" void kernel_launch(void* const* d_in, const int* in_sizes, int n_in,
                              void* d_out, int out_size)
{
    const int*   inp   = (const int*)d_in[0];     // (16384, 51) int32
    const float* table = (const float*)d_in[1];   // (100002, 64) float32
    float*       out   = (float*)d_out;           // (16384, 3264) float32

    const int threads = 256;                 // 8 warps/block
    const int total_threads = BATCH * 32;    // one warp per row
    const int blocks = (total_threads + threads - 1) / threads;
    cond_filter_kernel<<<blocks, threads>>>(inp, table, out);
}